// round 12
// baseline (speedup 1.0000x reference)
#include <cuda_runtime.h>
#include <cuda_fp16.h>
#include <cstdint>

// out[t,s] = sum_{k<=t} sum_a A[k,s,a] * us[t-k,a]
// GEMM: C[s,t] = sum_{k,a} A[k,s,a] * Upad[t+128-k, a]
// mma.sync.m16n8k16, single fp16 chain (rel_err ~2.7e-4 measured).
// R12: stall-structure round (R11 ncu: tensor 33.9%, issue 33.9%,
// nothing saturated -> latency-bound).
//  1. Register double-buffered ldmatrix fragments: kb+1's LDSMs issue
//     before kb's MMAs -> LDSM->MMA RAW chain hidden under 8 HMMAs.
//  2. ng permutation {0,3,1,2,3,0,2,1} balances causal live work per
//     SMSP (544/544 vs 512/576) -> no straggler at the iter barrier.
// Else unchanged: occ-2, 288 CTAs, K=64/iter, deferred-convert A
// pipeline, triple-buffered B cp.async, XOR-swizzled 128B rows,
// deterministic split-K partials + reduce.

#define KSPLIT 18
#define ATILE  8192           // 64 rows x 128 B
#define BTILE  16384          // 128 rows x 128 B
#define BOFF0  (2*ATILE)
#define SMEMT  (2*ATILE + 3*BTILE)   // 65536 B

__device__ float  g_partial[KSPLIT*128*1024];  // 9.4 MB
__device__ __half g_Uf[256*512];

__global__ __launch_bounds__(256) void prep_kernel(const float* __restrict__ us)
{
    int i = blockIdx.x*256 + threadIdx.x;   // 0..131071 over [256][512]
    int r = i >> 9, a = i & 511;
    float x = (r >= 128) ? us[(r-128)*512 + a] : 0.f;
    g_Uf[i] = __float2half_rn(x);
}

__global__ void dummy_kernel() {}

__device__ __forceinline__ void ldmx4(uint32_t* r, uint32_t addr) {
    asm volatile("ldmatrix.sync.aligned.m8n8.x4.shared.b16 {%0,%1,%2,%3}, [%4];"
        : "=r"(r[0]), "=r"(r[1]), "=r"(r[2]), "=r"(r[3]) : "r"(addr));
}
__device__ __forceinline__ void mma16816(float* c, const uint32_t* a, const uint32_t* b) {
    asm volatile("mma.sync.aligned.m16n8k16.row.col.f32.f16.f16.f32 "
        "{%0,%1,%2,%3}, {%4,%5,%6,%7}, {%8,%9}, {%0,%1,%2,%3};"
        : "+f"(c[0]), "+f"(c[1]), "+f"(c[2]), "+f"(c[3])
        : "r"(a[0]), "r"(a[1]), "r"(a[2]), "r"(a[3]), "r"(b[0]), "r"(b[1]));
}
__device__ __forceinline__ void cpa16(uint32_t dst, const void* src) {
    asm volatile("cp.async.cg.shared.global [%0], [%1], 16;" :: "r"(dst), "l"(src));
}
__device__ __forceinline__ uint32_t packh(float a, float b) {
    __half2 h = __floats2half2_rn(a, b);
    return *reinterpret_cast<uint32_t*>(&h);
}

// k-set for group g (0..17): t even: 36*(t/2)+g ; t odd: 36*((t+1)/2)-1-g ;
// t==7 (only g>=16): 143-g  -> covers all k in [0,128) once, cost-balanced.
__device__ __forceinline__ int kof(int g, int i) {
    const int t = i >> 3;
    if (t == 7) return 143 - g;
    return (t & 1) ? (36*((t+1) >> 1) - 1 - g) : (36*(t >> 1) + g);
}

__global__ __launch_bounds__(256, 2)
void mma_kernel(const float* __restrict__ A)
{
    extern __shared__ char smem[];
    const uint32_t smb = (uint32_t)__cvta_generic_to_shared(smem);

    const int tid  = threadIdx.x;
    const int wid  = tid >> 5;
    const int lane = tid & 31;
    const int wm   = wid >> 2;    // 2 m-groups of 32 (wid 0-3 -> 0, 4-7 -> 1)
    // SMSP-balanced n-group permutation: SMSP pairs get ng {0,3},{1,2},
    // {0,2}? -> {0,3,1,2,3,0,2,1}: SMSP0:(0,3) SMSP1:(3,0)? wid&3 pairs
    // (0,4):(0,3) (1,5):(3,0) (2,6):(1,2) (3,7):(2,1) -> each sums 544.
    const int NGT[8] = {0, 3, 1, 2, 3, 0, 2, 1};
    const int ng   = NGT[wid];
    const int s0   = blockIdx.x * 64;
    const int g    = blockIdx.y;
    const int NIT  = (g >= 16) ? 64 : 56;

    // A loader: 16 threads/row, rows rowgrp+16*jj (jj 0..3)
    const int rowgrp = tid >> 4;        // 0..15
    const int lane16 = tid & 15;
    // B loader: 2 threads per row
    const int brow  = tid >> 1;         // 0..127
    const int bhalf = tid & 1;

    // ldmatrix geometry (16B-unit XOR swizzle on 128B rows)
    const int arow  = wm*32 + (lane & 15);                        // 0..63
    const int axor  = arow & 7;
    const int asel  = lane >> 4;
    const int browl = 8*ng + (lane & 7) + 32*((lane >> 4) & 1);   // 0..127
    const int bxor  = lane & 7;
    const int bsel  = (lane >> 3) & 1;

    float acc[2][4][4];
#pragma unroll
    for (int im = 0; im < 2; im++)
#pragma unroll
        for (int j = 0; j < 4; j++)
#pragma unroll
            for (int c = 0; c < 4; c++) acc[im][j][c] = 0.f;

    float rF[16];     // raw fp32 A (loaded iter i, converted end of iter i)
    uint2 rH[4];      // packed fp16 A (STS'd top of iter i+1)

    auto ldgF = [&](int i) {
        const int k  = kof(g, i);
        const int a0 = (i & 7) << 6;
#pragma unroll
        for (int jj = 0; jj < 4; jj++) {
            const int grow = s0 + rowgrp + 16*jj;
            float4 v = *reinterpret_cast<const float4*>(
                A + ((size_t)k*1024 + grow)*512 + a0 + lane16*4);
            rF[4*jj+0] = v.x; rF[4*jj+1] = v.y; rF[4*jj+2] = v.z; rF[4*jj+3] = v.w;
        }
    };
    auto cvtA = [&]() {
#pragma unroll
        for (int jj = 0; jj < 4; jj++)
            rH[jj] = make_uint2(packh(rF[4*jj+0], rF[4*jj+1]),
                                packh(rF[4*jj+2], rF[4*jj+3]));
    };
    auto stsA = [&](int buf) {
        const int unit = lane16 >> 1;
        const int sub  = (lane16 & 1) * 8;
#pragma unroll
        for (int jj = 0; jj < 4; jj++) {
            const int row = rowgrp + 16*jj;
            *reinterpret_cast<uint2*>(smem + buf*ATILE + row*128 +
                                      ((unit ^ (row & 7)) << 4) + sub) = rH[jj];
        }
    };
    auto cpB = [&](int i, int buf) {
        const int k  = kof(g, i);
        const int a0 = (i & 7) << 6;
        const __half* src = g_Uf + (size_t)(brow + 128 - k)*512 + a0;
        const uint32_t dst = smb + BOFF0 + buf*BTILE + brow*128;
        const int rx = brow & 7;
#pragma unroll
        for (int c = 0; c < 4; c++) {
            const int u = bhalf*4 + c;
            cpa16(dst + ((u ^ rx) << 4), src + u*8);
        }
    };

    // ---- prologue ----
    cpB(0, 0); asm volatile("cp.async.commit_group;" ::: "memory");
    cpB(1, 1); asm volatile("cp.async.commit_group;" ::: "memory");
    ldgF(0); cvtA(); stsA(0);
    ldgF(1); cvtA();

    // ---- main loop (NIT iterations, K=64 each) ----
    for (int i = 0; i < NIT; i++) {
        const int abuf = i & 1;
        const int bbuf = i % 3;
        const int k    = kof(g, i);

        if (i < NIT-1) asm volatile("cp.async.wait_group 1;" ::: "memory");
        else           asm volatile("cp.async.wait_group 0;" ::: "memory");
        __syncthreads();

        if (i + 1 < NIT) stsA((i + 1) & 1);
        if (i + 2 < NIT) {
            ldgF(i + 2);
            cpB(i + 2, (i + 2) % 3);
            asm volatile("cp.async.commit_group;" ::: "memory");
        }

        // causal liveness: n8-tile j covers n in [(4j+ng)*8, +8)
        bool lv[4];
#pragma unroll
        for (int j = 0; j < 4; j++)
            lv[j] = (k < ((4*j + ng) << 3) + 8);
        bool lp[2];
#pragma unroll
        for (int p = 0; p < 2; p++)
            lp[p] = lv[2*p + 1];      // lv monotone increasing in j

        const uint32_t ab = smb + abuf*ATILE + arow*128;
        const uint32_t bb = smb + BOFF0 + bbuf*BTILE + browl*128;

        // register double-buffered fragments: LDSM for kb+1 issues
        // before the MMAs of kb (hides LDSM->MMA latency).
        uint32_t ah[2][2][4], uf[2][2][4];
        auto ldfrag = [&](int kb, int pb) {
            const int au = 2*kb + asel;
            ldmx4(ah[pb][0], ab +        ((au ^ axor) << 4));
            ldmx4(ah[pb][1], ab + 2048 + ((au ^ axor) << 4));
            const int bu = 2*kb + bsel;
            const uint32_t bsw = (uint32_t)((bu ^ bxor) << 4);
#pragma unroll
            for (int p = 0; p < 2; p++)
                if (lp[p]) ldmx4(uf[pb][p], bb + p*8192 + bsw);
        };

        ldfrag(0, 0);
#pragma unroll
        for (int kb = 0; kb < 4; kb++) {
            const int pb = kb & 1;
            if (kb < 3) ldfrag(kb + 1, pb ^ 1);
#pragma unroll
            for (int im = 0; im < 2; im++)
#pragma unroll
                for (int j = 0; j < 4; j++)
                    if (lv[j])
                        mma16816(acc[im][j], ah[pb][im], &uf[pb][j >> 1][(j & 1) * 2]);
        }

        if (i + 2 < NIT) cvtA();
    }

    // ---- epilogue: write split-K partials [g][t][s] ----
    float* pb = g_partial + (size_t)g * 131072;
    const int sidx = s0 + wm*32 + (lane >> 2);
#pragma unroll
    for (int im = 0; im < 2; im++) {
        const int sr = sidx + im*16;
#pragma unroll
        for (int j = 0; j < 4; j++) {
            const int n = ((4*j + ng) << 3) + (lane & 3) * 2;
            pb[(size_t)n      * 1024 + sr]     = acc[im][j][0];
            pb[(size_t)(n+1)  * 1024 + sr]     = acc[im][j][1];
            pb[(size_t)n      * 1024 + sr + 8] = acc[im][j][2];
            pb[(size_t)(n+1)  * 1024 + sr + 8] = acc[im][j][3];
        }
    }
}

__global__ __launch_bounds__(256) void reduce_kernel(float* __restrict__ out)
{
    int i = blockIdx.x*256 + threadIdx.x;   // 0..131071 floats
    float s = 0.f;
#pragma unroll
    for (int gg = 0; gg < KSPLIT; gg++)
        s += g_partial[(size_t)gg*131072 + i];
    out[i] = s;
}

extern "C" void kernel_launch(void* const* d_in, const int* in_sizes, int n_in,
                              void* d_out, int out_size)
{
    const float* us = (const float*)d_in[0];   // [128, 512]
    const float* A  = (const float*)d_in[1];   // [128, 1024, 512]
    if (n_in >= 2 && in_sizes[0] > in_sizes[1]) {
        const float* t = us; us = A; A = t;
    }
    cudaFuncSetAttribute(mma_kernel, cudaFuncAttributeMaxDynamicSharedMemorySize, SMEMT);

    prep_kernel<<<512, 256>>>(us);
    dummy_kernel<<<1, 1>>>();
    dummy_kernel<<<1, 1>>>();
    mma_kernel<<<dim3(16, KSPLIT), 256, SMEMT>>>(A);
    reduce_kernel<<<512, 256>>>((float*)d_out);
}